// round 4
// baseline (speedup 1.0000x reference)
#include <cuda_runtime.h>
#include <cstdint>

#define TB 64
#define TT 2048
#define TC 96
#define TS 256
#define TL 513            // 2*TS+1
#define NEGF (-1e30f)
#define LOG2E 1.4426950408889634f
#define LN2   0.6931471805599453f

#define NTH 544           // 17 warps; threads 0..512 own trellis states
#define ND  8             // row ring buffers (power of 2)
#define PD  7             // prefetch depth (ND-1)

// log-softmax denominators, in log2 domain: lse2[b,t] = log2(sum_c exp(x))
__device__ float g_lse[TB * TT];

__device__ __forceinline__ float ex2f_(float x) {
    float r; asm("ex2.approx.f32 %0, %1;" : "=f"(r) : "f"(x)); return r;
}
__device__ __forceinline__ float lg2f_(float x) {
    float r; asm("lg2.approx.f32 %0, %1;" : "=f"(r) : "f"(x)); return r;
}

// ---------------------------------------------------------------------------
// Kernel A: per-(b,t) log-sum-exp over C=96 classes. One warp per row.
// ---------------------------------------------------------------------------
__global__ void lse_kernel(const float* __restrict__ x) {
    int row = blockIdx.x * 4 + (threadIdx.x >> 5);
    if (row >= TB * TT) return;
    int lane = threadIdx.x & 31;
    const float* p = x + (size_t)row * TC;
    float v0 = p[lane], v1 = p[lane + 32], v2 = p[lane + 64];
    float m = fmaxf(fmaxf(v0, v1), v2);
    #pragma unroll
    for (int o = 16; o; o >>= 1) m = fmaxf(m, __shfl_xor_sync(0xffffffffu, m, o));
    float s = ex2f_((v0 - m) * LOG2E) + ex2f_((v1 - m) * LOG2E) + ex2f_((v2 - m) * LOG2E);
    #pragma unroll
    for (int o = 16; o; o >>= 1) s += __shfl_xor_sync(0xffffffffu, s, o);
    if (lane == 0) g_lse[row] = m * LOG2E + lg2f_(s);   // log2 domain
}

// ---------------------------------------------------------------------------
// Zero the scalar output (harness poisons d_out).
// ---------------------------------------------------------------------------
__global__ void zero_kernel(float* o) { if (threadIdx.x == 0) *o = 0.0f; }

// ---------------------------------------------------------------------------
// Kernel B: one CTA per batch element; alpha recursion over T steps.
// ---------------------------------------------------------------------------
__global__ void __launch_bounds__(NTH, 1) ctc_kernel(
    const float* __restrict__ x,       // [B,T,C]
    const int*   __restrict__ tgt32,   // targets viewed as 32-bit words
    const int*   __restrict__ tmask,   // [B,S] int32
    float*       __restrict__ out)
{
    __shared__ __align__(16) float rowbuf[ND][100];   // 96 logits + [96]=lse2
    __shared__ float alphaBuf[2][TL + 2];             // +2 leading NEG pads
    __shared__ int   lab[TS];
    __shared__ int   tlen_sh;

    const int tid = threadIdx.x;
    const int b   = blockIdx.x;

    // --- detect int32 vs int64 target storage (labels are >=1, so the
    //     second 32-bit word is 0 iff layout is little-endian int64) ---
    const bool is64 = (tgt32[1] == 0);
    const int stride = is64 ? 2 : 1;
    const int* trow = tgt32 + (size_t)b * TS * stride;
    if (tid < TS) lab[tid] = trow[tid * stride];
    if (tid == 0) tlen_sh = 0;
    if (tid < 2) { alphaBuf[0][tid] = NEGF; alphaBuf[1][tid] = NEGF; }
    __syncthreads();

    // --- target length = sum of mask row ---
    if (tid < TS) {
        int m = tmask[b * TS + tid];
        #pragma unroll
        for (int o = 16; o; o >>= 1) m += __shfl_xor_sync(0xffffffffu, m, o);
        if ((tid & 31) == 0) atomicAdd(&tlen_sh, m);
    }

    // --- per-thread trellis state config ---
    const int s = tid;
    const bool active = (s < TL);
    int  cls  = 0;       // extended label class for state s (blank = 0)
    bool skip = false;   // skip-transition allowed
    if (active && (s & 1)) {
        int j = s >> 1;                       // s odd: j = (s-1)/2
        cls  = lab[j];
        skip = (cls != 0) && (j == 0 || lab[j] != lab[j - 1]);
    }

    const float* xb   = x + (size_t)b * TT * TC;
    const float* lseb = g_lse + (size_t)b * TT;

    // --- prefetch rows 0..PD-1 (one commit_group each) ---
    for (int t = 0; t < PD; ++t) {
        float* dst = rowbuf[t & (ND - 1)];
        unsigned sa = (unsigned)__cvta_generic_to_shared(dst);
        if (tid < 24) {
            asm volatile("cp.async.ca.shared.global [%0], [%1], 16;"
                         :: "r"(sa + tid * 16), "l"(xb + (size_t)t * TC + tid * 4));
        } else if (tid == 24) {
            asm volatile("cp.async.ca.shared.global [%0], [%1], 4;"
                         :: "r"(sa + 96 * 4), "l"(lseb + t));
        }
        asm volatile("cp.async.commit_group;");
    }

    int cur = 0;
    for (int t = 0; t < TT; ++t) {
        asm volatile("cp.async.wait_group 6;");
        __syncthreads();   // row t visible to all; alpha(t-1) writes visible

        // prefetch row t+PD into slot previously holding row t-1 (safe now)
        {
            int tp = t + PD;
            if (tp < TT) {
                float* dst = rowbuf[tp & (ND - 1)];
                unsigned sa = (unsigned)__cvta_generic_to_shared(dst);
                if (tid < 24) {
                    asm volatile("cp.async.ca.shared.global [%0], [%1], 16;"
                                 :: "r"(sa + tid * 16), "l"(xb + (size_t)tp * TC + tid * 4));
                } else if (tid == 24) {
                    asm volatile("cp.async.ca.shared.global [%0], [%1], 4;"
                                 :: "r"(sa + 96 * 4), "l"(lseb + tp));
                }
            }
            asm volatile("cp.async.commit_group;");
        }

        const float* R = rowbuf[t & (ND - 1)];
        if (active) {
            float lse2 = R[96];
            float lp2  = fmaf(R[cls], LOG2E, -lse2);     // log2 p(class|t)
            float v;
            if (t == 0) {
                v = (s < 2) ? lp2 : NEGF;
            } else {
                const float* A = alphaBuf[cur] + 2;
                float a  = A[s];
                float pb = A[s - 1];
                float pc = skip ? A[s - 2] : NEGF;       // pads keep s<2 safe
                float m  = fmaxf(a, fmaxf(pb, pc));
                float sum = ex2f_(a - m) + ex2f_(pb - m) + ex2f_(pc - m);
                v = m + lg2f_(sum) + lp2;
            }
            alphaBuf[cur ^ 1][2 + s] = v;
        }
        cur ^= 1;
    }

    __syncthreads();
    if (tid == 0) {
        const float* A = alphaBuf[cur] + 2;
        int len = tlen_sh;
        float v1 = A[2 * len];
        float v2 = A[2 * len - 1];
        float m  = fmaxf(v1, v2);
        float la = m + lg2f_(ex2f_(v1 - m) + ex2f_(v2 - m));
        float loss = -la * LN2;                           // back to natural log
        if (!isfinite(loss) || loss >= 1e29f) loss = 0.0f;
        atomicAdd(out, loss / ((float)len * (float)TB));
    }
}

// ---------------------------------------------------------------------------
extern "C" void kernel_launch(void* const* d_in, const int* in_sizes, int n_in,
                              void* d_out, int out_size) {
    const float* x     = (const float*)d_in[0];   // predictions [B,T,C] f32
    const int*   tgt   = (const int*)  d_in[1];   // targets (int32 or int64 words)
    // d_in[2]: predictions_mask — unused (full-length trellis per reference)
    const int*   tmask = (const int*)  d_in[3];   // targets_mask [B,S] i32
    float* out = (float*)d_out;

    zero_kernel<<<1, 32>>>(out);
    lse_kernel<<<(TB * TT + 3) / 4, 128>>>(x);
    ctc_kernel<<<TB, NTH>>>(x, tgt, tmask, out);
}

// round 5
// speedup vs baseline: 1.3662x; 1.3662x over previous
#include <cuda_runtime.h>
#include <cstdint>

#define TB 64
#define TT 2048
#define TC 96
#define TS 256
#define TL 513            // 2*TS+1
#define NEGF (-1e30f)
#define LOG2E 1.4426950408889634f
#define LN2   0.6931471805599453f

#define NTH 288           // 9 warps; threads 0..256 own state pairs
#define NA  257           // active threads (thread i owns states 2i, 2i+1)
#define NCH (TT / 8)      // number of 8-row chunks

// log-softmax denominators, log2 domain: lse2[b,t] = log2(sum_c exp(x))
__device__ float g_lse[TB * TT];

__device__ __forceinline__ float ex2f_(float x) {
    float r; asm("ex2.approx.f32 %0, %1;" : "=f"(r) : "f"(x)); return r;
}
__device__ __forceinline__ float lg2f_(float x) {
    float r; asm("lg2.approx.f32 %0, %1;" : "=f"(r) : "f"(x)); return r;
}

// 2-way LSE in log2 domain: max + lg2(1 + 2^(min-max))
__device__ __forceinline__ float lse2f_(float a, float b) {
    float m = fmaxf(a, b);
    float n = fminf(a, b);
    return m + lg2f_(1.0f + ex2f_(n - m));
}
// 3-way LSE: sort (max/mid/min), skip the ex2 of the max term (==1)
__device__ __forceinline__ float lse3f_(float a, float b, float c) {
    float s1 = fmaxf(a, b), t1 = fminf(a, b);
    float m  = fmaxf(s1, c);
    float md = fmaxf(fminf(s1, c), t1);
    float mn = fminf(t1, c);
    return m + lg2f_(1.0f + ex2f_(md - m) + ex2f_(mn - m));
}

// ---------------------------------------------------------------------------
// Kernel A: per-(b,t) log-sum-exp over C=96. One warp per row.
// ---------------------------------------------------------------------------
__global__ void lse_kernel(const float* __restrict__ x) {
    int row = blockIdx.x * 4 + (threadIdx.x >> 5);
    if (row >= TB * TT) return;
    int lane = threadIdx.x & 31;
    const float* p = x + (size_t)row * TC;
    float v0 = p[lane], v1 = p[lane + 32], v2 = p[lane + 64];
    float m = fmaxf(fmaxf(v0, v1), v2);
    #pragma unroll
    for (int o = 16; o; o >>= 1) m = fmaxf(m, __shfl_xor_sync(0xffffffffu, m, o));
    float s = ex2f_((v0 - m) * LOG2E) + ex2f_((v1 - m) * LOG2E) + ex2f_((v2 - m) * LOG2E);
    #pragma unroll
    for (int o = 16; o; o >>= 1) s += __shfl_xor_sync(0xffffffffu, s, o);
    if (lane == 0) g_lse[row] = m * LOG2E + lg2f_(s);
}

__global__ void zero_kernel(float* o) { if (threadIdx.x == 0) *o = 0.0f; }

// ---------------------------------------------------------------------------
// Kernel B: one CTA per batch element; alpha recursion, 2 states per thread.
// ---------------------------------------------------------------------------
__global__ void __launch_bounds__(NTH, 1) ctc_kernel(
    const float* __restrict__ x,       // [B,T,C]
    const int*   __restrict__ tgt32,   // targets viewed as 32-bit words
    const int*   __restrict__ tmask,   // [B,S] int32
    float*       __restrict__ out)
{
    // 8-row chunk ring: 8*96 logits + 8 lse values per chunk
    __shared__ __align__(16) float bufc[3][8 * TC + 8];   // 776 floats each
    __shared__ float shO[2][NA + 1];   // odd-alpha exchange, [i+1] = thread i's aO
    __shared__ float shE[NA];          // final even alphas
    __shared__ int   lab[TS];
    __shared__ int   tlen_sh;

    const int tid = threadIdx.x;
    const int b   = blockIdx.x;

    // int32 vs int64 target storage (labels >= 1 => high word 0 iff int64 LE)
    const bool is64 = (tgt32[1] == 0);
    const int  stride = is64 ? 2 : 1;
    const int* trow = tgt32 + (size_t)b * TS * stride;
    if (tid < TS) lab[tid] = trow[tid * stride];
    if (tid == 0) { tlen_sh = 0; shO[0][0] = NEGF; shO[1][0] = NEGF; }
    __syncthreads();

    if (tid < TS) {
        int m = tmask[b * TS + tid];
        #pragma unroll
        for (int o = 16; o; o >>= 1) m += __shfl_xor_sync(0xffffffffu, m, o);
        if ((tid & 31) == 0) atomicAdd(&tlen_sh, m);
    }

    // per-thread config: states 2i (blank) and 2i+1 (label lab[i])
    const int  i      = tid;
    const bool active = (i < NA);
    int  cls  = 0;
    bool skip = false;
    if (active && i < TS) {
        cls  = lab[i];
        skip = (i > 0) && (lab[i] != lab[i - 1]);
    }

    const float* xb   = x + (size_t)b * TT * TC;
    const float* lseb = g_lse + (size_t)b * TT;

    // chunk prefetch: 8 rows = 3072B logits + 32B lse, one commit_group
    auto issue_chunk = [&](int c) {
        if (c < NCH) {
            unsigned sa = (unsigned)__cvta_generic_to_shared(bufc[c % 3]);
            if (tid < 192) {
                asm volatile("cp.async.ca.shared.global [%0], [%1], 16;"
                             :: "r"(sa + tid * 16), "l"(xb + (size_t)c * 768 + tid * 4));
            } else if (tid < 194) {
                int k = tid - 192;
                asm volatile("cp.async.ca.shared.global [%0], [%1], 16;"
                             :: "r"(sa + 768 * 4 + k * 16), "l"(lseb + c * 8 + k * 4));
            }
        }
        asm volatile("cp.async.commit_group;");
    };

    issue_chunk(0);
    issue_chunk(1);

    float aE = NEGF, aO = NEGF;
    int cur = 0;

    // ---- t = 0 (peeled) ----
    asm volatile("cp.async.wait_group 1;");
    __syncthreads();
    issue_chunk(2);
    {
        const float* R = bufc[0];
        if (active) {
            float lse2 = R[8 * TC + 0];
            if (i == 0) {
                aE = fmaf(R[0],   LOG2E, -lse2);
                aO = fmaf(R[cls], LOG2E, -lse2);
            }
            shO[0][i + 1] = aO;
        }
    }

    // ---- main loop t = 1 .. T-1 ----
    for (int t = 1; t < TT; ++t) {
        if ((t & 7) == 0) asm volatile("cp.async.wait_group 1;");
        __syncthreads();
        if ((t & 7) == 0) issue_chunk((t >> 3) + 2);

        const float* R = bufc[(t >> 3) % 3] + (t & 7) * TC;
        const float* Rl = bufc[(t >> 3) % 3] + 8 * TC;
        if (active) {
            float lse2  = Rl[t & 7];
            float leftO = shO[cur][i];
            float lpB = fmaf(R[0],   LOG2E, -lse2);
            float lpO = fmaf(R[cls], LOG2E, -lse2);
            float newE = lse2f_(aE, leftO) + lpB;                     // state 2i
            float c3   = skip ? leftO : NEGF;
            float newO = lse3f_(aO, aE, c3) + lpO;                    // state 2i+1
            aE = newE; aO = newO;
            shO[cur ^ 1][i + 1] = aO;
        }
        cur ^= 1;
    }

    if (active) shE[i] = aE;
    __syncthreads();

    if (tid == 0) {
        int len = tlen_sh;
        float loss = 0.0f;
        if (len >= 1 && len <= TS) {
            float v1 = shE[len];             // alpha[2*len]   (thread len, even)
            float v2 = shO[cur][len];        // alpha[2*len-1] (thread len-1, odd)
            float la = lse2f_(v1, v2);
            loss = -la * LN2;
            if (!isfinite(loss) || loss >= 1e29f) loss = 0.0f;
            loss = loss / ((float)len * (float)TB);
        }
        atomicAdd(out, loss);
    }
}

// ---------------------------------------------------------------------------
extern "C" void kernel_launch(void* const* d_in, const int* in_sizes, int n_in,
                              void* d_out, int out_size) {
    const float* x     = (const float*)d_in[0];   // predictions [B,T,C] f32
    const int*   tgt   = (const int*)  d_in[1];   // targets (int32 or int64 words)
    // d_in[2]: predictions_mask — unused (full-length trellis per reference)
    const int*   tmask = (const int*)  d_in[3];   // targets_mask [B,S] i32
    float* out = (float*)d_out;

    zero_kernel<<<1, 32>>>(out);
    lse_kernel<<<(TB * TT + 3) / 4, 128>>>(x);
    ctc_kernel<<<TB, NTH>>>(x, tgt, tmask, out);
}